// round 4
// baseline (speedup 1.0000x reference)
#include <cuda_runtime.h>
#include <cuda_bf16.h>
#include <cstdint>

#define HID 128
#define NHEAD 8
#define HD 16
#define MAXN 50000
#define MAXE 500000

typedef unsigned long long ull;

// ---------------- static device scratch ----------------
__device__ float g_q[MAXN * HID];
__device__ float g_k[MAXN * HID];
__device__ float g_v[MAXN * HID];
__device__ float g_xr[MAXN * HID];
__device__ float g_num[MAXN * HID];
__device__ float g_z[MAXN * NHEAD];
__device__ int   g_is64;
// 5 weights (q,k,v,skip,e): transposed (B[n][k]) + pre-swizzled bf16 hi/lo blobs
__device__ __nv_bfloat16 g_wt[5][2][128 * 128];

// ---------------- helpers ----------------
__device__ __forceinline__ uint32_t smem_u32(const void* p) {
    uint32_t a;
    asm("{ .reg .u64 t; cvta.to.shared.u64 t, %1; cvt.u32.u64 %0, t; }" : "=r"(a) : "l"(p));
    return a;
}

// blocked SW128 byte offset for element (row, col) of a [128 x 128] bf16 tile:
// two 64-col blocks of 16KB; within a block rows are 128B apart; XOR swizzle.
__device__ __forceinline__ uint32_t swz_off(int row, int col) {
    uint32_t off = ((uint32_t)(col >> 6) << 14) + ((uint32_t)row << 7) + ((uint32_t)(col & 63) << 1);
    return off ^ ((off >> 3) & 0x70);
}

__device__ __forceinline__ void ldsm4(uint32_t* r, uint32_t addr) {
    asm volatile("ldmatrix.sync.aligned.m8n8.x4.shared.b16 {%0,%1,%2,%3}, [%4];"
                 : "=r"(r[0]), "=r"(r[1]), "=r"(r[2]), "=r"(r[3]) : "r"(addr));
}

__device__ __forceinline__ void mma_bf16(float* d, const uint32_t* a, uint32_t b0, uint32_t b1) {
    asm("mma.sync.aligned.m16n8k16.row.col.f32.bf16.bf16.f32 "
        "{%0,%1,%2,%3}, {%4,%5,%6,%7}, {%8,%9}, {%0,%1,%2,%3};"
        : "+f"(d[0]), "+f"(d[1]), "+f"(d[2]), "+f"(d[3])
        : "r"(a[0]), "r"(a[1]), "r"(a[2]), "r"(a[3]), "r"(b0), "r"(b1));
}

// smem layout (dynamic)
#define SM_AHI  0
#define SM_ALO  32768
#define SM_BHI  65536
#define SM_BLO  98304
#define SM_TOTAL 131072
// edge epilogue reuses smem from SM_AHI as es[128][132] floats (67584 B)

// ---------------- small kernels ----------------
__global__ void detect_kernel(const void* idx, long long total_elems) {
    if (threadIdx.x == 0 && blockIdx.x == 0) {
        const long long* p = (const long long*)idx;
        long long n = total_elems / 2;
        if (n > 256) n = 256;
        int is64 = 1;
        for (long long i = 0; i < n; i++) {
            long long v = p[i];
            if (v < 0 || v >= (1LL << 31)) is64 = 0;
        }
        g_is64 = is64;
    }
}

__global__ void zero_kernel(int N) {
    int stride = gridDim.x * blockDim.x;
    int i = blockIdx.x * blockDim.x + threadIdx.x;
    int tot = N * HID;
    for (int k = i; k < tot; k += stride) g_num[k] = 0.f;
    int tz = N * NHEAD;
    for (int k = i; k < tz; k += stride) g_z[k] = 0.f;
}

// transpose W ([in=128, out=128] row-major) -> B[n][k] = W[k][n], hi/lo bf16, pre-swizzled
__global__ void prep_w_kernel(const float* W0, const float* W1, const float* W2,
                              const float* W3, const float* W4) {
    const float* W = W0;
    if (blockIdx.x == 1) W = W1;
    else if (blockIdx.x == 2) W = W2;
    else if (blockIdx.x == 3) W = W3;
    else if (blockIdx.x == 4) W = W4;
    char* hi = (char*)g_wt[blockIdx.x][0];
    char* lo = (char*)g_wt[blockIdx.x][1];
    for (int i = threadIdx.x; i < 128 * 128; i += blockDim.x) {
        int n = i & 127, k = i >> 7;
        float x = W[k * 128 + n];               // coalesced over n
        __nv_bfloat16 h = __float2bfloat16(x);
        __nv_bfloat16 l = __float2bfloat16(x - __bfloat162float(h));
        uint32_t sw = swz_off(n, k);
        *(__nv_bfloat16*)(hi + sw) = h;
        *(__nv_bfloat16*)(lo + sw) = l;
    }
}

// ---------------- staging helpers ----------------
// convert A tile [128 x 128] f32 -> bf16 hi/lo into swizzled smem
__device__ __forceinline__ void stage_A(const float* __restrict__ Asrc, int rows_valid,
                                        char* sm, int tid)
{
    char* Ahi = sm + SM_AHI;
    char* Alo = sm + SM_ALO;
    for (int i = tid; i < 4096; i += 256) {
        int r = i >> 5;
        int c4 = (i & 31) << 2;
        float4 x;
        if (r < rows_valid) x = *(const float4*)(Asrc + (size_t)r * HID + c4);
        else x = make_float4(0.f, 0.f, 0.f, 0.f);
        __nv_bfloat162 h01, h23, l01, l23;
        float hx, hy;
        h01.x = __float2bfloat16(x.x); hx = __bfloat162float(h01.x);
        h01.y = __float2bfloat16(x.y); hy = __bfloat162float(h01.y);
        l01.x = __float2bfloat16(x.x - hx);
        l01.y = __float2bfloat16(x.y - hy);
        h23.x = __float2bfloat16(x.z); hx = __bfloat162float(h23.x);
        h23.y = __float2bfloat16(x.w); hy = __bfloat162float(h23.y);
        l23.x = __float2bfloat16(x.z - hx);
        l23.y = __float2bfloat16(x.w - hy);
        uint32_t sw = swz_off(r, c4);
        *(__nv_bfloat162*)(Ahi + sw)     = h01;
        *(__nv_bfloat162*)(Ahi + sw + 4) = h23;
        *(__nv_bfloat162*)(Alo + sw)     = l01;
        *(__nv_bfloat162*)(Alo + sw + 4) = l23;
    }
}

__device__ __forceinline__ void stage_B(const __nv_bfloat16* __restrict__ wblob,
                                        char* sm, int tid)
{
    const float4* src = (const float4*)wblob;   // hi 32KB || lo 32KB
    float4* dst = (float4*)(sm + SM_BHI);
    for (int i = tid; i < 4096; i += 256) dst[i] = src[i];
}

// ---------------- HMMA mainloop: 3-pass bf16 hi/lo split ----------------
// warp tile 32x64 at (mw, nw); acc[2][8][4] fp32
__device__ __forceinline__ void hmma_loop(uint32_t smb, int lane, int mw, int nw,
                                          float acc[2][8][4])
{
#pragma unroll
    for (int mi = 0; mi < 2; mi++)
#pragma unroll
        for (int nj = 0; nj < 8; nj++)
#pragma unroll
            for (int t = 0; t < 4; t++) acc[mi][nj][t] = 0.f;

    int arow = mw + (lane & 15);
    int acoff = (lane >> 4) << 3;
    int brow = nw + ((lane >> 4) << 3) + (lane & 7);
    int bcoff = lane & 8;

#pragma unroll
    for (int ks = 0; ks < 8; ks++) {
        int k0 = ks * 16;
        uint32_t aoff0 = swz_off(arow, k0 + acoff);
        uint32_t aoff1 = swz_off(arow + 16, k0 + acoff);
        uint32_t ahi[2][4], alo[2][4];
        ldsm4(ahi[0], smb + SM_AHI + aoff0);
        ldsm4(ahi[1], smb + SM_AHI + aoff1);
        ldsm4(alo[0], smb + SM_ALO + aoff0);
        ldsm4(alo[1], smb + SM_ALO + aoff1);

        uint32_t bhi[4][4], blo[4][4];
#pragma unroll
        for (int p = 0; p < 4; p++) {
            uint32_t boff = swz_off(brow + p * 16, k0 + bcoff);
            ldsm4(bhi[p], smb + SM_BHI + boff);
            ldsm4(blo[p], smb + SM_BLO + boff);
        }

#pragma unroll
        for (int mi = 0; mi < 2; mi++) {
#pragma unroll
            for (int nj = 0; nj < 8; nj++) {
                int p = nj >> 1, h = (nj & 1) * 2;
                mma_bf16(acc[mi][nj], ahi[mi], bhi[p][h], bhi[p][h + 1]);   // hi*hi
                mma_bf16(acc[mi][nj], ahi[mi], blo[p][h], blo[p][h + 1]);   // hi*lo
                mma_bf16(acc[mi][nj], alo[mi], bhi[p][h], bhi[p][h + 1]);   // lo*hi
            }
        }
    }
}

// ---------------- node kernel: 4 fused projections ----------------
__global__ __launch_bounds__(256, 1) void node_hmma_kernel(
    const float* __restrict__ X,
    const float* __restrict__ bq, const float* __restrict__ bk,
    const float* __restrict__ bv, const float* __restrict__ bs, int M)
{
    extern __shared__ char sm[];
    uint32_t smb = smem_u32(sm);
    int tid = threadIdx.x;
    int lane = tid & 31, w = tid >> 5;
    int mw = (w & 3) * 32, nw = (w >> 2) * 64;
    int mBase = blockIdx.x * 128;
    int rv = M - mBase; if (rv > 128) rv = 128;

    stage_A(X + (size_t)mBase * HID, rv, sm, tid);

    const float* biases[4] = {bq, bk, bv, bs};
    float* outs[4];
    {
        float *p0, *p1, *p2, *p3;
        // device-side symbol addresses: direct (g_q etc. are device arrays)
        p0 = g_q; p1 = g_k; p2 = g_v; p3 = g_xr;
        outs[0] = p0; outs[1] = p1; outs[2] = p2; outs[3] = p3;
    }

    for (int wi = 0; wi < 4; wi++) {
        __syncthreads();                 // protect B smem (prev mma reads done)
        stage_B(g_wt[wi][0], sm, tid);
        __syncthreads();

        float acc[2][8][4];
        hmma_loop(smb, lane, mw, nw, acc);

        const float* bias = biases[wi];
        float* out = outs[wi];
        int r0 = mBase + mw + (lane >> 2);
        int cbase = nw + (lane & 3) * 2;
#pragma unroll
        for (int mi = 0; mi < 2; mi++) {
#pragma unroll
            for (int nj = 0; nj < 8; nj++) {
                int c = cbase + nj * 8;
                float b0 = __ldg(bias + c), b1 = __ldg(bias + c + 1);
                int r = r0 + mi * 16;
                if (r < M) {
                    float2 v = make_float2(acc[mi][nj][0] + b0, acc[mi][nj][1] + b1);
                    *(float2*)(out + (size_t)r * HID + c) = v;
                }
                if (r + 8 < M) {
                    float2 v = make_float2(acc[mi][nj][2] + b0, acc[mi][nj][3] + b1);
                    *(float2*)(out + (size_t)(r + 8) * HID + c) = v;
                }
            }
        }
    }
}

// ---------------- edge kernel: e = angle @ We (HMMA) + fused attention scatter ----------------
__global__ __launch_bounds__(256, 1) void edge_hmma_kernel(
    const float* __restrict__ angle, const void* __restrict__ idx, int E)
{
    extern __shared__ char sm[];
    uint32_t smb = smem_u32(sm);
    int tid = threadIdx.x;
    int lane = tid & 31, w = tid >> 5;
    int mw = (w & 3) * 32, nw = (w >> 2) * 64;
    int eBase = blockIdx.x * 128;
    int rv = E - eBase; if (rv > 128) rv = 128;

    stage_A(angle + (size_t)eBase * HID, rv, sm, tid);
    stage_B(g_wt[4][0], sm, tid);
    __syncthreads();

    float acc[2][8][4];
    hmma_loop(smb, lane, mw, nw, acc);
    __syncthreads();                     // all smem reads done; reuse as es

    // spill e tile to smem: es[128][132]
    float* es = (float*)(sm + SM_AHI);
    {
        int r0 = mw + (lane >> 2);
        int cbase = nw + (lane & 3) * 2;
#pragma unroll
        for (int mi = 0; mi < 2; mi++) {
#pragma unroll
            for (int nj = 0; nj < 8; nj++) {
                int c = cbase + nj * 8;
                int r = r0 + mi * 16;
                *(float2*)(es + r * 132 + c)       = make_float2(acc[mi][nj][0], acc[mi][nj][1]);
                *(float2*)(es + (r + 8) * 132 + c) = make_float2(acc[mi][nj][2], acc[mi][nj][3]);
            }
        }
    }
    __syncthreads();

    // attention phase: 2 threads per edge, 4 heads (64 cols) per thread
    int j  = tid & 1;
    int el = tid >> 1;
    int eg = eBase + el;
    if (eg >= E) return;

    long long s, d;
    if (g_is64) {
        const long long* p = (const long long*)idx;
        s = p[eg]; d = p[eg + E];
    } else {
        const int* p = (const int*)idx;
        s = p[eg]; d = p[eg + E];
    }

    int jc = j * 64;
    const float* qr = g_q + (size_t)d * HID + jc;
    const float* kr = g_k + (size_t)s * HID + jc;
    const float* vr = g_v + (size_t)s * HID + jc;
    const float* er = es + el * 132 + jc;
    float* nr = g_num + (size_t)d * HID + jc;

    float av[4];
#pragma unroll
    for (int h = 0; h < 4; h++) {
        int base = h * 16;
        float alpha = 0.f;
#pragma unroll
        for (int c = 0; c < 4; c++) {
            float4 q4 = *(const float4*)(qr + base + c * 4);
            float4 k4 = *(const float4*)(kr + base + c * 4);
            float4 e4 = *(const float4*)(er + base + c * 4);
            alpha += q4.x * (k4.x + e4.x) + q4.y * (k4.y + e4.y)
                   + q4.z * (k4.z + e4.z) + q4.w * (k4.w + e4.w);
        }
        float a = __expf(alpha * 0.25f);   // /sqrt(16); no max-shift needed (alpha bounded)
        av[h] = a;
#pragma unroll
        for (int c = 0; c < 4; c++) {
            float4 v4 = *(const float4*)(vr + base + c * 4);
            float4 e4 = *(const float4*)(er + base + c * 4);
            float rx = a * (v4.x + e4.x);
            float ry = a * (v4.y + e4.y);
            float rz = a * (v4.z + e4.z);
            float rw = a * (v4.w + e4.w);
            asm volatile("red.global.add.v4.f32 [%0], {%1, %2, %3, %4};"
                         :: "l"(nr + base + c * 4),
                            "f"(rx), "f"(ry), "f"(rz), "f"(rw) : "memory");
        }
    }
    asm volatile("red.global.add.v4.f32 [%0], {%1, %2, %3, %4};"
                 :: "l"(g_z + (size_t)d * NHEAD + j * 4),
                    "f"(av[0]), "f"(av[1]), "f"(av[2]), "f"(av[3]) : "memory");
}

// ---------------- finalize: softmax div, beta gate, LN, relu, residual ----------------
__global__ __launch_bounds__(256) void finalize_kernel(
    const float* __restrict__ x, const float* __restrict__ Wbeta,
    const float* __restrict__ gamma, const float* __restrict__ lbeta,
    float* __restrict__ out, int N)
{
    int warp = threadIdx.x >> 5;
    int lane = threadIdx.x & 31;
    int n = blockIdx.x * 8 + warp;
    if (n >= N) return;
    int c = lane * 4;

    float4 num = *(const float4*)(g_num + (size_t)n * HID + c);
    float z = g_z[(size_t)n * NHEAD + (lane >> 2)];
    float inv = z > 0.f ? 1.f / z : 0.f;
    float4 o = make_float4(num.x * inv, num.y * inv, num.z * inv, num.w * inv);
    float4 xr = *(const float4*)(g_xr + (size_t)n * HID + c);

    float4 wb0 = *(const float4*)(Wbeta + c);
    float4 wb1 = *(const float4*)(Wbeta + 128 + c);
    float4 wb2 = *(const float4*)(Wbeta + 256 + c);
    float dot = o.x * wb0.x + o.y * wb0.y + o.z * wb0.z + o.w * wb0.w
              + xr.x * wb1.x + xr.y * wb1.y + xr.z * wb1.z + xr.w * wb1.w
              + (o.x - xr.x) * wb2.x + (o.y - xr.y) * wb2.y
              + (o.z - xr.z) * wb2.z + (o.w - xr.w) * wb2.w;
#pragma unroll
    for (int m = 16; m; m >>= 1) dot += __shfl_xor_sync(0xffffffffu, dot, m);
    float beta = 1.f / (1.f + __expf(-dot));

    float4 g;
    g.x = beta * xr.x + (1.f - beta) * o.x;
    g.y = beta * xr.y + (1.f - beta) * o.y;
    g.z = beta * xr.z + (1.f - beta) * o.z;
    g.w = beta * xr.w + (1.f - beta) * o.w;

    float sgm = g.x + g.y + g.z + g.w;
#pragma unroll
    for (int m = 16; m; m >>= 1) sgm += __shfl_xor_sync(0xffffffffu, sgm, m);
    float mu = sgm * (1.f / 128.f);

    float dx = g.x - mu, dy = g.y - mu, dz = g.z - mu, dw = g.w - mu;
    float vs = dx * dx + dy * dy + dz * dz + dw * dw;
#pragma unroll
    for (int m = 16; m; m >>= 1) vs += __shfl_xor_sync(0xffffffffu, vs, m);
    float rstd = rsqrtf(vs * (1.f / 128.f) + 1e-5f);

    float4 gm = *(const float4*)(gamma + c);
    float4 lb = *(const float4*)(lbeta + c);
    float4 xin = *(const float4*)(x + (size_t)n * HID + c);

    float4 res;
    float y;
    y = dx * rstd * gm.x + lb.x; res.x = xin.x + fmaxf(y, 0.f);
    y = dy * rstd * gm.y + lb.y; res.y = xin.y + fmaxf(y, 0.f);
    y = dz * rstd * gm.z + lb.z; res.z = xin.z + fmaxf(y, 0.f);
    y = dw * rstd * gm.w + lb.w; res.w = xin.w + fmaxf(y, 0.f);
    *(float4*)(out + (size_t)n * HID + c) = res;
}

// ---------------- launch ----------------
extern "C" void kernel_launch(void* const* d_in, const int* in_sizes, int n_in,
                              void* d_out, int out_size)
{
    const float* edge_state = (const float*)d_in[0];
    const void*  idx        = d_in[1];
    const float* angle      = (const float*)d_in[2];
    const float* Wq = (const float*)d_in[3];
    const float* bq = (const float*)d_in[4];
    const float* Wk = (const float*)d_in[5];
    const float* bk = (const float*)d_in[6];
    const float* Wv = (const float*)d_in[7];
    const float* bv = (const float*)d_in[8];
    const float* We = (const float*)d_in[9];
    const float* Ws = (const float*)d_in[10];
    const float* bs = (const float*)d_in[11];
    const float* Wbeta = (const float*)d_in[12];
    const float* gamma = (const float*)d_in[13];
    const float* lbeta = (const float*)d_in[14];

    int N = in_sizes[0] / HID;
    int E = in_sizes[2] / HID;

    cudaFuncSetAttribute(node_hmma_kernel, cudaFuncAttributeMaxDynamicSharedMemorySize, SM_TOTAL);
    cudaFuncSetAttribute(edge_hmma_kernel, cudaFuncAttributeMaxDynamicSharedMemorySize, SM_TOTAL);

    detect_kernel<<<1, 32>>>(idx, (long long)in_sizes[1]);
    zero_kernel<<<512, 256>>>(N);
    prep_w_kernel<<<5, 128>>>(Wq, Wk, Wv, Ws, We);

    node_hmma_kernel<<<(N + 127) / 128, 256, SM_TOTAL>>>(edge_state, bq, bk, bv, bs, N);

    edge_hmma_kernel<<<(E + 127) / 128, 256, SM_TOTAL>>>(angle, idx, E);

    finalize_kernel<<<(N + 7) / 8, 256>>>(edge_state, Wbeta, gamma, lbeta,
                                          (float*)d_out, N);
}

// round 5
// speedup vs baseline: 1.0528x; 1.0528x over previous
#include <cuda_runtime.h>
#include <cuda_bf16.h>
#include <cstdint>

#define HID 128
#define NHEAD 8
#define HD 16
#define MAXN 50000
#define MAXE 500000

typedef unsigned long long ull;

// ---------------- static device scratch ----------------
__device__ float g_q[MAXN * HID];
__device__ float g_k[MAXN * HID];
__device__ float g_v[MAXN * HID];
__device__ float g_xr[MAXN * HID];
__device__ float g_num[MAXN * HID];
__device__ float g_z[MAXN * NHEAD];
__device__ int   g_is64;
// 5 weights: 4 chunks each (hi-half0, hi-half1, lo-half0, lo-half1), 64x128 bf16 swizzled
__device__ __nv_bfloat16 g_wt[5][4][64 * 128];

// ---------------- helpers ----------------
__device__ __forceinline__ uint32_t smem_u32(const void* p) {
    uint32_t a;
    asm("{ .reg .u64 t; cvta.to.shared.u64 t, %1; cvt.u32.u64 %0, t; }" : "=r"(a) : "l"(p));
    return a;
}

// A tile [128 rows x 128 k] bf16: two 64-k blocks of 16KB, 128B rows, XOR swizzle
__device__ __forceinline__ uint32_t swzA(int row, int k) {
    uint32_t off = ((uint32_t)(k >> 6) << 14) + ((uint32_t)row << 7) + ((uint32_t)(k & 63) << 1);
    return off ^ ((off >> 3) & 0x70);
}
// B tile [64 rows x 128 k] bf16: two 64-k blocks of 8KB
__device__ __forceinline__ uint32_t swzB(int row, int k) {
    uint32_t off = ((uint32_t)(k >> 6) << 13) + ((uint32_t)row << 7) + ((uint32_t)(k & 63) << 1);
    return off ^ ((off >> 3) & 0x70);
}

__device__ __forceinline__ void ldsm4(uint32_t* r, uint32_t addr) {
    asm volatile("ldmatrix.sync.aligned.m8n8.x4.shared.b16 {%0,%1,%2,%3}, [%4];"
                 : "=r"(r[0]), "=r"(r[1]), "=r"(r[2]), "=r"(r[3]) : "r"(addr));
}

__device__ __forceinline__ void mma_bf16(float* d, const uint32_t* a, uint32_t b0, uint32_t b1) {
    asm("mma.sync.aligned.m16n8k16.row.col.f32.bf16.bf16.f32 "
        "{%0,%1,%2,%3}, {%4,%5,%6,%7}, {%8,%9}, {%0,%1,%2,%3};"
        : "+f"(d[0]), "+f"(d[1]), "+f"(d[2]), "+f"(d[3])
        : "r"(a[0]), "r"(a[1]), "r"(a[2]), "r"(a[3]), "r"(b0), "r"(b1));
}

// smem layout
#define SM_AHI  0
#define SM_ALO  32768
#define SM_BHI  65536
#define SM_BLO  81920
#define SM_ES   65536            // es half-tile overlays B region after mma
#define ES_STRIDE 68             // floats; 16B-aligned rows (68*4=272=16*17)
#define SM_TOTAL (65536 + 128 * ES_STRIDE * 4)   // 100352

// ---------------- small kernels ----------------
__global__ void detect_kernel(const void* idx, long long total_elems) {
    if (threadIdx.x == 0 && blockIdx.x == 0) {
        const long long* p = (const long long*)idx;
        long long n = total_elems / 2;
        if (n > 256) n = 256;
        int is64 = 1;
        for (long long i = 0; i < n; i++) {
            long long v = p[i];
            if (v < 0 || v >= (1LL << 31)) is64 = 0;
        }
        g_is64 = is64;
    }
}

__global__ void zero_kernel(int N) {
    int stride = gridDim.x * blockDim.x;
    int i = blockIdx.x * blockDim.x + threadIdx.x;
    int tot = N * HID;
    for (int k = i; k < tot; k += stride) g_num[k] = 0.f;
    int tz = N * NHEAD;
    for (int k = i; k < tz; k += stride) g_z[k] = 0.f;
}

// W ([in=128,out=128] row-major) -> B[n][k]=W[k][n]; hi/lo bf16; per-half swizzled chunks
__global__ void prep_w_kernel(const float* W0, const float* W1, const float* W2,
                              const float* W3, const float* W4) {
    const float* W = W0;
    if (blockIdx.x == 1) W = W1;
    else if (blockIdx.x == 2) W = W2;
    else if (blockIdx.x == 3) W = W3;
    else if (blockIdx.x == 4) W = W4;
    for (int i = threadIdx.x; i < 128 * 128; i += blockDim.x) {
        int n = i & 127, k = i >> 7;
        float x = W[k * 128 + n];               // coalesced over n
        __nv_bfloat16 hv = __float2bfloat16(x);
        __nv_bfloat16 lv = __float2bfloat16(x - __bfloat162float(hv));
        int half = n >> 6, n64 = n & 63;
        uint32_t sw = swzB(n64, k);
        *(__nv_bfloat16*)((char*)g_wt[blockIdx.x][half]     + sw) = hv;
        *(__nv_bfloat16*)((char*)g_wt[blockIdx.x][2 + half] + sw) = lv;
    }
}

// ---------------- staging ----------------
__device__ __forceinline__ void stage_A(const float* __restrict__ Asrc, int rows_valid,
                                        char* sm, int tid)
{
    char* Ahi = sm + SM_AHI;
    char* Alo = sm + SM_ALO;
    for (int i = tid; i < 4096; i += 256) {
        int r = i >> 5;
        int c4 = (i & 31) << 2;
        float4 x;
        if (r < rows_valid) x = *(const float4*)(Asrc + (size_t)r * HID + c4);
        else x = make_float4(0.f, 0.f, 0.f, 0.f);
        __nv_bfloat162 h01, h23, l01, l23;
        float hx, hy;
        h01.x = __float2bfloat16(x.x); hx = __bfloat162float(h01.x);
        h01.y = __float2bfloat16(x.y); hy = __bfloat162float(h01.y);
        l01.x = __float2bfloat16(x.x - hx);
        l01.y = __float2bfloat16(x.y - hy);
        h23.x = __float2bfloat16(x.z); hx = __bfloat162float(h23.x);
        h23.y = __float2bfloat16(x.w); hy = __bfloat162float(h23.y);
        l23.x = __float2bfloat16(x.z - hx);
        l23.y = __float2bfloat16(x.w - hy);
        uint32_t sw = swzA(r, c4);
        *(__nv_bfloat162*)(Ahi + sw)     = h01;
        *(__nv_bfloat162*)(Ahi + sw + 4) = h23;
        *(__nv_bfloat162*)(Alo + sw)     = l01;
        *(__nv_bfloat162*)(Alo + sw + 4) = l23;
    }
}

__device__ __forceinline__ void stage_B(int wi, int h, char* sm, int tid)
{
    const float4* sH = (const float4*)g_wt[wi][h];
    const float4* sL = (const float4*)g_wt[wi][2 + h];
    float4* dH = (float4*)(sm + SM_BHI);
    float4* dL = (float4*)(sm + SM_BLO);
    for (int i = tid; i < 1024; i += 256) { dH[i] = sH[i]; dL[i] = sL[i]; }
}

// ---------------- HMMA mainloop: warp tile 32x32, 3-pass bf16 hi/lo ----------------
__device__ __forceinline__ void hmma_loop(uint32_t smb, int lane, int wm, int wn,
                                          float acc[2][4][4])
{
#pragma unroll
    for (int mi = 0; mi < 2; mi++)
#pragma unroll
        for (int nj = 0; nj < 4; nj++)
#pragma unroll
            for (int t = 0; t < 4; t++) acc[mi][nj][t] = 0.f;

    int arow = wm + (lane & 15);
    int acoff = (lane >> 4) << 3;
    int brow = wn + ((lane >> 4) << 3) + (lane & 7);
    int bcoff = lane & 8;

#pragma unroll
    for (int ks = 0; ks < 8; ks++) {
        int k0 = ks * 16;
        uint32_t aoff0 = swzA(arow, k0 + acoff);
        uint32_t aoff1 = swzA(arow + 16, k0 + acoff);
        uint32_t ahi[2][4], alo[2][4];
        ldsm4(ahi[0], smb + SM_AHI + aoff0);
        ldsm4(ahi[1], smb + SM_AHI + aoff1);
        ldsm4(alo[0], smb + SM_ALO + aoff0);
        ldsm4(alo[1], smb + SM_ALO + aoff1);

        uint32_t bhi[2][4], blo[2][4];
#pragma unroll
        for (int p = 0; p < 2; p++) {
            uint32_t boff = swzB(brow + p * 16, k0 + bcoff);
            ldsm4(bhi[p], smb + SM_BHI + boff);
            ldsm4(blo[p], smb + SM_BLO + boff);
        }

#pragma unroll
        for (int mi = 0; mi < 2; mi++) {
#pragma unroll
            for (int nj = 0; nj < 4; nj++) {
                int p = nj >> 1, hh = (nj & 1) * 2;
                mma_bf16(acc[mi][nj], ahi[mi], bhi[p][hh], bhi[p][hh + 1]);
                mma_bf16(acc[mi][nj], ahi[mi], blo[p][hh], blo[p][hh + 1]);
                mma_bf16(acc[mi][nj], alo[mi], bhi[p][hh], bhi[p][hh + 1]);
            }
        }
    }
}

// ---------------- node kernel: 4 fused projections, BN=64 halves ----------------
__global__ __launch_bounds__(256, 2) void node_hmma_kernel(
    const float* __restrict__ X,
    const float* __restrict__ bq, const float* __restrict__ bk,
    const float* __restrict__ bv, const float* __restrict__ bs, int M)
{
    extern __shared__ char sm[];
    uint32_t smb = smem_u32(sm);
    int tid = threadIdx.x;
    int lane = tid & 31, w = tid >> 5;
    int wm = (w & 3) * 32, wn = (w >> 2) * 32;
    int mBase = blockIdx.x * 128;
    int rv = M - mBase; if (rv > 128) rv = 128;

    stage_A(X + (size_t)mBase * HID, rv, sm, tid);

    const float* biases[4] = {bq, bk, bv, bs};
    float* outs[4] = {g_q, g_k, g_v, g_xr};

#pragma unroll 1
    for (int wi = 0; wi < 4; wi++) {
#pragma unroll 1
        for (int h = 0; h < 2; h++) {
            __syncthreads();                 // B region free (prev mma reads done)
            stage_B(wi, h, sm, tid);
            __syncthreads();

            float acc[2][4][4];
            hmma_loop(smb, lane, wm, wn, acc);

            const float* bias = biases[wi];
            float* out = outs[wi];
            int r0 = mBase + wm + (lane >> 2);
            int cbase = h * 64 + wn + (lane & 3) * 2;
#pragma unroll
            for (int mi = 0; mi < 2; mi++) {
#pragma unroll
                for (int nj = 0; nj < 4; nj++) {
                    int c = cbase + nj * 8;
                    float b0 = __ldg(bias + c), b1 = __ldg(bias + c + 1);
                    int r = r0 + mi * 16;
                    if (r < M)
                        *(float2*)(out + (size_t)r * HID + c) =
                            make_float2(acc[mi][nj][0] + b0, acc[mi][nj][1] + b1);
                    if (r + 8 < M)
                        *(float2*)(out + (size_t)(r + 8) * HID + c) =
                            make_float2(acc[mi][nj][2] + b0, acc[mi][nj][3] + b1);
                }
            }
        }
    }
}

// ---------------- edge kernel: per-half e GEMM + fused attention ----------------
__global__ __launch_bounds__(256, 2) void edge_hmma_kernel(
    const float* __restrict__ angle, const void* __restrict__ idx, int E)
{
    extern __shared__ char sm[];
    uint32_t smb = smem_u32(sm);
    int tid = threadIdx.x;
    int lane = tid & 31, w = tid >> 5;
    int wm = (w & 3) * 32, wn = (w >> 2) * 32;
    int eBase = blockIdx.x * 128;
    int rv = E - eBase; if (rv > 128) rv = 128;

    stage_A(angle + (size_t)eBase * HID, rv, sm, tid);

    // per-thread edge assignment for attention: 2 threads/edge
    int j  = tid & 1;
    int el = tid >> 1;
    int eg = eBase + el;
    bool ok = eg < E;
    long long s = 0, d = 0;
    if (ok) {
        if (g_is64) {
            const long long* p = (const long long*)idx;
            s = p[eg]; d = p[eg + E];
        } else {
            const int* p = (const int*)idx;
            s = p[eg]; d = p[eg + E];
        }
    }

#pragma unroll 1
    for (int h = 0; h < 2; h++) {
        __syncthreads();                 // es / B region free
        stage_B(4, h, sm, tid);
        __syncthreads();

        float acc[2][4][4];
        hmma_loop(smb, lane, wm, wn, acc);
        __syncthreads();                 // all B reads done; reuse region as es

        // spill e half-tile: es[128][ES_STRIDE]
        float* es = (float*)(sm + SM_ES);
        {
            int r0 = wm + (lane >> 2);
            int cbase = wn + (lane & 3) * 2;
#pragma unroll
            for (int mi = 0; mi < 2; mi++) {
#pragma unroll
                for (int nj = 0; nj < 4; nj++) {
                    int c = cbase + nj * 8;
                    int r = r0 + mi * 16;
                    *(float2*)(es + r * ES_STRIDE + c) =
                        make_float2(acc[mi][nj][0], acc[mi][nj][1]);
                    *(float2*)(es + (r + 8) * ES_STRIDE + c) =
                        make_float2(acc[mi][nj][2], acc[mi][nj][3]);
                }
            }
        }
        __syncthreads();

        // attention for heads [h*4, h*4+4); this thread: local heads {2j, 2j+1}
        if (ok) {
            int cglob = h * 64 + j * 32;       // global col base (2 heads = 32 cols)
            const float* qr = g_q + (size_t)d * HID + cglob;
            const float* kr = g_k + (size_t)s * HID + cglob;
            const float* vr = g_v + (size_t)s * HID + cglob;
            const float* er = es + el * ES_STRIDE + j * 32;
            float* nr = g_num + (size_t)d * HID + cglob;

            float av[2];
#pragma unroll
            for (int t = 0; t < 2; t++) {
                int base = t * 16;
                float alpha = 0.f;
#pragma unroll
                for (int c = 0; c < 4; c++) {
                    float4 q4 = *(const float4*)(qr + base + c * 4);
                    float4 k4 = *(const float4*)(kr + base + c * 4);
                    float4 e4 = *(const float4*)(er + base + c * 4);
                    alpha += q4.x * (k4.x + e4.x) + q4.y * (k4.y + e4.y)
                           + q4.z * (k4.z + e4.z) + q4.w * (k4.w + e4.w);
                }
                float a = __expf(alpha * 0.25f);   // /sqrt(16); no max-shift (alpha bounded)
                av[t] = a;
#pragma unroll
                for (int c = 0; c < 4; c++) {
                    float4 v4 = *(const float4*)(vr + base + c * 4);
                    float4 e4 = *(const float4*)(er + base + c * 4);
                    float rx = a * (v4.x + e4.x);
                    float ry = a * (v4.y + e4.y);
                    float rz = a * (v4.z + e4.z);
                    float rw = a * (v4.w + e4.w);
                    asm volatile("red.global.add.v4.f32 [%0], {%1, %2, %3, %4};"
                                 :: "l"(nr + base + c * 4),
                                    "f"(rx), "f"(ry), "f"(rz), "f"(rw) : "memory");
                }
            }
            asm volatile("red.global.add.v2.f32 [%0], {%1, %2};"
                         :: "l"(g_z + (size_t)d * NHEAD + h * 4 + j * 2),
                            "f"(av[0]), "f"(av[1]) : "memory");
        }
    }
}

// ---------------- finalize ----------------
__global__ __launch_bounds__(256) void finalize_kernel(
    const float* __restrict__ x, const float* __restrict__ Wbeta,
    const float* __restrict__ gamma, const float* __restrict__ lbeta,
    float* __restrict__ out, int N)
{
    int warp = threadIdx.x >> 5;
    int lane = threadIdx.x & 31;
    int n = blockIdx.x * 8 + warp;
    if (n >= N) return;
    int c = lane * 4;

    float4 num = *(const float4*)(g_num + (size_t)n * HID + c);
    float z = g_z[(size_t)n * NHEAD + (lane >> 2)];
    float inv = z > 0.f ? 1.f / z : 0.f;
    float4 o = make_float4(num.x * inv, num.y * inv, num.z * inv, num.w * inv);
    float4 xr = *(const float4*)(g_xr + (size_t)n * HID + c);

    float4 wb0 = *(const float4*)(Wbeta + c);
    float4 wb1 = *(const float4*)(Wbeta + 128 + c);
    float4 wb2 = *(const float4*)(Wbeta + 256 + c);
    float dot = o.x * wb0.x + o.y * wb0.y + o.z * wb0.z + o.w * wb0.w
              + xr.x * wb1.x + xr.y * wb1.y + xr.z * wb1.z + xr.w * wb1.w
              + (o.x - xr.x) * wb2.x + (o.y - xr.y) * wb2.y
              + (o.z - xr.z) * wb2.z + (o.w - xr.w) * wb2.w;
#pragma unroll
    for (int m = 16; m; m >>= 1) dot += __shfl_xor_sync(0xffffffffu, dot, m);
    float beta = 1.f / (1.f + __expf(-dot));

    float4 g;
    g.x = beta * xr.x + (1.f - beta) * o.x;
    g.y = beta * xr.y + (1.f - beta) * o.y;
    g.z = beta * xr.z + (1.f - beta) * o.z;
    g.w = beta * xr.w + (1.f - beta) * o.w;

    float sgm = g.x + g.y + g.z + g.w;
#pragma unroll
    for (int m = 16; m; m >>= 1) sgm += __shfl_xor_sync(0xffffffffu, sgm, m);
    float mu = sgm * (1.f / 128.f);

    float dx = g.x - mu, dy = g.y - mu, dz = g.z - mu, dw = g.w - mu;
    float vs = dx * dx + dy * dy + dz * dz + dw * dw;
#pragma unroll
    for (int m = 16; m; m >>= 1) vs += __shfl_xor_sync(0xffffffffu, vs, m);
    float rstd = rsqrtf(vs * (1.f / 128.f) + 1e-5f);

    float4 gm = *(const float4*)(gamma + c);
    float4 lb = *(const float4*)(lbeta + c);
    float4 xin = *(const float4*)(x + (size_t)n * HID + c);

    float4 res;
    float y;
    y = dx * rstd * gm.x + lb.x; res.x = xin.x + fmaxf(y, 0.f);
    y = dy * rstd * gm.y + lb.y; res.y = xin.y + fmaxf(y, 0.f);
    y = dz * rstd * gm.z + lb.z; res.z = xin.z + fmaxf(y, 0.f);
    y = dw * rstd * gm.w + lb.w; res.w = xin.w + fmaxf(y, 0.f);
    *(float4*)(out + (size_t)n * HID + c) = res;
}

// ---------------- launch ----------------
extern "C" void kernel_launch(void* const* d_in, const int* in_sizes, int n_in,
                              void* d_out, int out_size)
{
    const float* edge_state = (const float*)d_in[0];
    const void*  idx        = d_in[1];
    const float* angle      = (const float*)d_in[2];
    const float* Wq = (const float*)d_in[3];
    const float* bq = (const float*)d_in[4];
    const float* Wk = (const float*)d_in[5];
    const float* bk = (const float*)d_in[6];
    const float* Wv = (const float*)d_in[7];
    const float* bv = (const float*)d_in[8];
    const float* We = (const float*)d_in[9];
    const float* Ws = (const float*)d_in[10];
    const float* bs = (const float*)d_in[11];
    const float* Wbeta = (const float*)d_in[12];
    const float* gamma = (const float*)d_in[13];
    const float* lbeta = (const float*)d_in[14];

    int N = in_sizes[0] / HID;
    int E = in_sizes[2] / HID;

    cudaFuncSetAttribute(node_hmma_kernel, cudaFuncAttributeMaxDynamicSharedMemorySize, SM_TOTAL);
    cudaFuncSetAttribute(edge_hmma_kernel, cudaFuncAttributeMaxDynamicSharedMemorySize, SM_TOTAL);

    detect_kernel<<<1, 32>>>(idx, (long long)in_sizes[1]);
    zero_kernel<<<512, 256>>>(N);
    prep_w_kernel<<<5, 128>>>(Wq, Wk, Wv, Ws, We);

    node_hmma_kernel<<<(N + 127) / 128, 256, SM_TOTAL>>>(edge_state, bq, bk, bv, bs, N);

    edge_hmma_kernel<<<(E + 127) / 128, 256, SM_TOTAL>>>(angle, idx, E);

    finalize_kernel<<<(N + 7) / 8, 256>>>(edge_state, Wbeta, gamma, lbeta,
                                          (float*)d_out, N);
}

// round 6
// speedup vs baseline: 1.2339x; 1.1720x over previous
#include <cuda_runtime.h>
#include <cuda_bf16.h>
#include <cstdint>

#define HID 128
#define NHEAD 8
#define HD 16
#define MAXN 50000
#define MAXE 500000

typedef unsigned long long ull;

// ---------------- static device scratch ----------------
__device__ float g_q[MAXN * HID];
__device__ float g_k[MAXN * HID];
__device__ float g_v[MAXN * HID];
__device__ float g_xr[MAXN * HID];
__device__ float g_num[MAXN * HID];
__device__ float g_z[MAXN * NHEAD];
__device__ float g_e[(size_t)MAXE * HID];     // 256MB streaming e buffer
__device__ int   g_is64;
// 5 weights: 4 chunks each (hi-half0, hi-half1, lo-half0, lo-half1), 64x128 bf16 swizzled
__device__ __nv_bfloat16 g_wt[5][4][64 * 128];

// ---------------- helpers ----------------
__device__ __forceinline__ uint32_t smem_u32(const void* p) {
    uint32_t a;
    asm("{ .reg .u64 t; cvta.to.shared.u64 t, %1; cvt.u32.u64 %0, t; }" : "=r"(a) : "l"(p));
    return a;
}

// A tile [128 rows x 128 k] bf16: two 64-k blocks of 16KB, 128B rows, XOR swizzle
__device__ __forceinline__ uint32_t swzA(int row, int k) {
    uint32_t off = ((uint32_t)(k >> 6) << 14) + ((uint32_t)row << 7) + ((uint32_t)(k & 63) << 1);
    return off ^ ((off >> 3) & 0x70);
}
// B tile [64 rows x 128 k] bf16: two 64-k blocks of 8KB
__device__ __forceinline__ uint32_t swzB(int row, int k) {
    uint32_t off = ((uint32_t)(k >> 6) << 13) + ((uint32_t)row << 7) + ((uint32_t)(k & 63) << 1);
    return off ^ ((off >> 3) & 0x70);
}

__device__ __forceinline__ void ldsm4(uint32_t* r, uint32_t addr) {
    asm volatile("ldmatrix.sync.aligned.m8n8.x4.shared.b16 {%0,%1,%2,%3}, [%4];"
                 : "=r"(r[0]), "=r"(r[1]), "=r"(r[2]), "=r"(r[3]) : "r"(addr));
}

__device__ __forceinline__ void mma_bf16(float* d, const uint32_t* a, uint32_t b0, uint32_t b1) {
    asm("mma.sync.aligned.m16n8k16.row.col.f32.bf16.bf16.f32 "
        "{%0,%1,%2,%3}, {%4,%5,%6,%7}, {%8,%9}, {%0,%1,%2,%3};"
        : "+f"(d[0]), "+f"(d[1]), "+f"(d[2]), "+f"(d[3])
        : "r"(a[0]), "r"(a[1]), "r"(a[2]), "r"(a[3]), "r"(b0), "r"(b1));
}

// smem layout (GEMM kernels)
#define SM_AHI  0
#define SM_ALO  32768
#define SM_BHI  65536
#define SM_BLO  81920
#define SM_TOTAL 98304

// ---------------- small kernels ----------------
__global__ void detect_kernel(const void* idx, long long total_elems) {
    if (threadIdx.x == 0 && blockIdx.x == 0) {
        const long long* p = (const long long*)idx;
        long long n = total_elems / 2;
        if (n > 256) n = 256;
        int is64 = 1;
        for (long long i = 0; i < n; i++) {
            long long v = p[i];
            if (v < 0 || v >= (1LL << 31)) is64 = 0;
        }
        g_is64 = is64;
    }
}

__global__ void zero_kernel(int N) {
    int stride = gridDim.x * blockDim.x;
    int i = blockIdx.x * blockDim.x + threadIdx.x;
    int tot = N * HID;
    for (int k = i; k < tot; k += stride) g_num[k] = 0.f;
    int tz = N * NHEAD;
    for (int k = i; k < tz; k += stride) g_z[k] = 0.f;
}

// W ([in=128,out=128] row-major) -> B[n][k]=W[k][n]; hi/lo bf16; per-half swizzled chunks
__global__ void prep_w_kernel(const float* W0, const float* W1, const float* W2,
                              const float* W3, const float* W4) {
    const float* W = W0;
    if (blockIdx.x == 1) W = W1;
    else if (blockIdx.x == 2) W = W2;
    else if (blockIdx.x == 3) W = W3;
    else if (blockIdx.x == 4) W = W4;
    for (int i = threadIdx.x; i < 128 * 128; i += blockDim.x) {
        int n = i & 127, k = i >> 7;
        float x = W[k * 128 + n];               // coalesced over n
        __nv_bfloat16 hv = __float2bfloat16(x);
        __nv_bfloat16 lv = __float2bfloat16(x - __bfloat162float(hv));
        int half = n >> 6, n64 = n & 63;
        uint32_t sw = swzB(n64, k);
        *(__nv_bfloat16*)((char*)g_wt[blockIdx.x][half]     + sw) = hv;
        *(__nv_bfloat16*)((char*)g_wt[blockIdx.x][2 + half] + sw) = lv;
    }
}

// ---------------- staging ----------------
__device__ __forceinline__ void stage_A(const float* __restrict__ Asrc, int rows_valid,
                                        char* sm, int tid)
{
    char* Ahi = sm + SM_AHI;
    char* Alo = sm + SM_ALO;
    for (int i = tid; i < 4096; i += 256) {
        int r = i >> 5;
        int c4 = (i & 31) << 2;
        float4 x;
        if (r < rows_valid) x = *(const float4*)(Asrc + (size_t)r * HID + c4);
        else x = make_float4(0.f, 0.f, 0.f, 0.f);
        __nv_bfloat162 h01, h23, l01, l23;
        float hx, hy;
        h01.x = __float2bfloat16(x.x); hx = __bfloat162float(h01.x);
        h01.y = __float2bfloat16(x.y); hy = __bfloat162float(h01.y);
        l01.x = __float2bfloat16(x.x - hx);
        l01.y = __float2bfloat16(x.y - hy);
        h23.x = __float2bfloat16(x.z); hx = __bfloat162float(h23.x);
        h23.y = __float2bfloat16(x.w); hy = __bfloat162float(h23.y);
        l23.x = __float2bfloat16(x.z - hx);
        l23.y = __float2bfloat16(x.w - hy);
        uint32_t sw = swzA(r, c4);
        *(__nv_bfloat162*)(Ahi + sw)     = h01;
        *(__nv_bfloat162*)(Ahi + sw + 4) = h23;
        *(__nv_bfloat162*)(Alo + sw)     = l01;
        *(__nv_bfloat162*)(Alo + sw + 4) = l23;
    }
}

__device__ __forceinline__ void stage_B(int wi, int h, char* sm, int tid)
{
    const float4* sH = (const float4*)g_wt[wi][h];
    const float4* sL = (const float4*)g_wt[wi][2 + h];
    float4* dH = (float4*)(sm + SM_BHI);
    float4* dL = (float4*)(sm + SM_BLO);
    for (int i = tid; i < 1024; i += 256) { dH[i] = sH[i]; dL[i] = sL[i]; }
}

// ---------------- HMMA mainloop: warp tile 32x32, 3-pass bf16 hi/lo ----------------
__device__ __forceinline__ void hmma_loop(uint32_t smb, int lane, int wm, int wn,
                                          float acc[2][4][4])
{
#pragma unroll
    for (int mi = 0; mi < 2; mi++)
#pragma unroll
        for (int nj = 0; nj < 4; nj++)
#pragma unroll
            for (int t = 0; t < 4; t++) acc[mi][nj][t] = 0.f;

    int arow = wm + (lane & 15);
    int acoff = (lane >> 4) << 3;
    int brow = wn + ((lane >> 4) << 3) + (lane & 7);
    int bcoff = lane & 8;

#pragma unroll
    for (int ks = 0; ks < 8; ks++) {
        int k0 = ks * 16;
        uint32_t aoff0 = swzA(arow, k0 + acoff);
        uint32_t aoff1 = swzA(arow + 16, k0 + acoff);
        uint32_t ahi[2][4], alo[2][4];
        ldsm4(ahi[0], smb + SM_AHI + aoff0);
        ldsm4(ahi[1], smb + SM_AHI + aoff1);
        ldsm4(alo[0], smb + SM_ALO + aoff0);
        ldsm4(alo[1], smb + SM_ALO + aoff1);

        uint32_t bhi[2][4], blo[2][4];
#pragma unroll
        for (int p = 0; p < 2; p++) {
            uint32_t boff = swzB(brow + p * 16, k0 + bcoff);
            ldsm4(bhi[p], smb + SM_BHI + boff);
            ldsm4(blo[p], smb + SM_BLO + boff);
        }

#pragma unroll
        for (int mi = 0; mi < 2; mi++) {
#pragma unroll
            for (int nj = 0; nj < 4; nj++) {
                int p = nj >> 1, hh = (nj & 1) * 2;
                mma_bf16(acc[mi][nj], ahi[mi], bhi[p][hh], bhi[p][hh + 1]);
                mma_bf16(acc[mi][nj], ahi[mi], blo[p][hh], blo[p][hh + 1]);
                mma_bf16(acc[mi][nj], alo[mi], bhi[p][hh], bhi[p][hh + 1]);
            }
        }
    }
}

// ---------------- node kernel: 4 fused projections, BN=64 halves ----------------
__global__ __launch_bounds__(256, 2) void node_hmma_kernel(
    const float* __restrict__ X,
    const float* __restrict__ bq, const float* __restrict__ bk,
    const float* __restrict__ bv, const float* __restrict__ bs, int M)
{
    extern __shared__ char sm[];
    uint32_t smb = smem_u32(sm);
    int tid = threadIdx.x;
    int lane = tid & 31, w = tid >> 5;
    int wm = (w & 3) * 32, wn = (w >> 2) * 32;
    int mBase = blockIdx.x * 128;
    int rv = M - mBase; if (rv > 128) rv = 128;

    stage_A(X + (size_t)mBase * HID, rv, sm, tid);

    const float* biases[4] = {bq, bk, bv, bs};
    float* outs[4] = {g_q, g_k, g_v, g_xr};

#pragma unroll 1
    for (int wi = 0; wi < 4; wi++) {
#pragma unroll 1
        for (int h = 0; h < 2; h++) {
            __syncthreads();
            stage_B(wi, h, sm, tid);
            __syncthreads();

            float acc[2][4][4];
            hmma_loop(smb, lane, wm, wn, acc);

            const float* bias = biases[wi];
            float* out = outs[wi];
            int r0 = mBase + wm + (lane >> 2);
            int cbase = h * 64 + wn + (lane & 3) * 2;
#pragma unroll
            for (int mi = 0; mi < 2; mi++) {
#pragma unroll
                for (int nj = 0; nj < 4; nj++) {
                    int c = cbase + nj * 8;
                    float b0 = __ldg(bias + c), b1 = __ldg(bias + c + 1);
                    int r = r0 + mi * 16;
                    if (r < M)
                        *(float2*)(out + (size_t)r * HID + c) =
                            make_float2(acc[mi][nj][0] + b0, acc[mi][nj][1] + b1);
                    if (r + 8 < M)
                        *(float2*)(out + (size_t)(r + 8) * HID + c) =
                            make_float2(acc[mi][nj][2] + b0, acc[mi][nj][3] + b1);
                }
            }
        }
    }
}

// ---------------- e-GEMM kernel: e = angle @ We -> g_e (streaming stores) ----------------
__global__ __launch_bounds__(256, 2) void egemm_hmma_kernel(
    const float* __restrict__ angle, int E)
{
    extern __shared__ char sm[];
    uint32_t smb = smem_u32(sm);
    int tid = threadIdx.x;
    int lane = tid & 31, w = tid >> 5;
    int wm = (w & 3) * 32, wn = (w >> 2) * 32;
    int eBase = blockIdx.x * 128;
    int rv = E - eBase; if (rv > 128) rv = 128;

    stage_A(angle + (size_t)eBase * HID, rv, sm, tid);

#pragma unroll 1
    for (int h = 0; h < 2; h++) {
        __syncthreads();
        stage_B(4, h, sm, tid);
        __syncthreads();

        float acc[2][4][4];
        hmma_loop(smb, lane, wm, wn, acc);

        int r0 = eBase + wm + (lane >> 2);
        int cbase = h * 64 + wn + (lane & 3) * 2;
#pragma unroll
        for (int mi = 0; mi < 2; mi++) {
#pragma unroll
            for (int nj = 0; nj < 4; nj++) {
                int c = cbase + nj * 8;
                int r = r0 + mi * 16;
                if (r < E)
                    __stcs((float2*)(g_e + (size_t)r * HID + c),
                           make_float2(acc[mi][nj][0], acc[mi][nj][1]));
                if (r + 8 < E)
                    __stcs((float2*)(g_e + (size_t)(r + 8) * HID + c),
                           make_float2(acc[mi][nj][2], acc[mi][nj][3]));
            }
        }
    }
}

// ---------------- attention kernel: high occupancy gather/scatter ----------------
// 4 threads per edge; thread j handles cols [j*32, j*32+32) = heads 2j, 2j+1
__global__ __launch_bounds__(256) void attn_kernel(const void* __restrict__ idx, int E)
{
    int t = blockIdx.x * 256 + threadIdx.x;
    int eg = t >> 2;
    int j = t & 3;
    if (eg >= E) return;

    long long s, d;
    if (g_is64) {
        const long long* p = (const long long*)idx;
        s = p[eg]; d = p[eg + E];
    } else {
        const int* p = (const int*)idx;
        s = p[eg]; d = p[eg + E];
    }

    int jc = j * 32;
    const float* qr = g_q + (size_t)d * HID + jc;
    const float* kr = g_k + (size_t)s * HID + jc;
    const float* vr = g_v + (size_t)s * HID + jc;
    const float* er = g_e + (size_t)eg * HID + jc;
    float* nr = g_num + (size_t)d * HID + jc;

    float av[2];
#pragma unroll
    for (int hh = 0; hh < 2; hh++) {
        int base = hh * 16;
        float4 e4[4], v4[4];
        float alpha = 0.f;
#pragma unroll
        for (int c = 0; c < 4; c++) {
            e4[c] = __ldcs((const float4*)(er + base + c * 4));
            float4 q4 = *(const float4*)(qr + base + c * 4);
            float4 k4 = *(const float4*)(kr + base + c * 4);
            v4[c] = *(const float4*)(vr + base + c * 4);
            alpha += q4.x * (k4.x + e4[c].x) + q4.y * (k4.y + e4[c].y)
                   + q4.z * (k4.z + e4[c].z) + q4.w * (k4.w + e4[c].w);
        }
        float a = __expf(alpha * 0.25f);   // /sqrt(16); no max-shift (alpha bounded)
        av[hh] = a;
#pragma unroll
        for (int c = 0; c < 4; c++) {
            float rx = a * (v4[c].x + e4[c].x);
            float ry = a * (v4[c].y + e4[c].y);
            float rz = a * (v4[c].z + e4[c].z);
            float rw = a * (v4[c].w + e4[c].w);
            asm volatile("red.global.add.v4.f32 [%0], {%1, %2, %3, %4};"
                         :: "l"(nr + base + c * 4),
                            "f"(rx), "f"(ry), "f"(rz), "f"(rw) : "memory");
        }
    }
    asm volatile("red.global.add.v2.f32 [%0], {%1, %2};"
                 :: "l"(g_z + (size_t)d * NHEAD + j * 2),
                    "f"(av[0]), "f"(av[1]) : "memory");
}

// ---------------- finalize ----------------
__global__ __launch_bounds__(256) void finalize_kernel(
    const float* __restrict__ x, const float* __restrict__ Wbeta,
    const float* __restrict__ gamma, const float* __restrict__ lbeta,
    float* __restrict__ out, int N)
{
    int warp = threadIdx.x >> 5;
    int lane = threadIdx.x & 31;
    int n = blockIdx.x * 8 + warp;
    if (n >= N) return;
    int c = lane * 4;

    float4 num = *(const float4*)(g_num + (size_t)n * HID + c);
    float z = g_z[(size_t)n * NHEAD + (lane >> 2)];
    float inv = z > 0.f ? 1.f / z : 0.f;
    float4 o = make_float4(num.x * inv, num.y * inv, num.z * inv, num.w * inv);
    float4 xr = *(const float4*)(g_xr + (size_t)n * HID + c);

    float4 wb0 = *(const float4*)(Wbeta + c);
    float4 wb1 = *(const float4*)(Wbeta + 128 + c);
    float4 wb2 = *(const float4*)(Wbeta + 256 + c);
    float dot = o.x * wb0.x + o.y * wb0.y + o.z * wb0.z + o.w * wb0.w
              + xr.x * wb1.x + xr.y * wb1.y + xr.z * wb1.z + xr.w * wb1.w
              + (o.x - xr.x) * wb2.x + (o.y - xr.y) * wb2.y
              + (o.z - xr.z) * wb2.z + (o.w - xr.w) * wb2.w;
#pragma unroll
    for (int m = 16; m; m >>= 1) dot += __shfl_xor_sync(0xffffffffu, dot, m);
    float beta = 1.f / (1.f + __expf(-dot));

    float4 g;
    g.x = beta * xr.x + (1.f - beta) * o.x;
    g.y = beta * xr.y + (1.f - beta) * o.y;
    g.z = beta * xr.z + (1.f - beta) * o.z;
    g.w = beta * xr.w + (1.f - beta) * o.w;

    float sgm = g.x + g.y + g.z + g.w;
#pragma unroll
    for (int m = 16; m; m >>= 1) sgm += __shfl_xor_sync(0xffffffffu, sgm, m);
    float mu = sgm * (1.f / 128.f);

    float dx = g.x - mu, dy = g.y - mu, dz = g.z - mu, dw = g.w - mu;
    float vs = dx * dx + dy * dy + dz * dz + dw * dw;
#pragma unroll
    for (int m = 16; m; m >>= 1) vs += __shfl_xor_sync(0xffffffffu, vs, m);
    float rstd = rsqrtf(vs * (1.f / 128.f) + 1e-5f);

    float4 gm = *(const float4*)(gamma + c);
    float4 lb = *(const float4*)(lbeta + c);
    float4 xin = *(const float4*)(x + (size_t)n * HID + c);

    float4 res;
    float y;
    y = dx * rstd * gm.x + lb.x; res.x = xin.x + fmaxf(y, 0.f);
    y = dy * rstd * gm.y + lb.y; res.y = xin.y + fmaxf(y, 0.f);
    y = dz * rstd * gm.z + lb.z; res.z = xin.z + fmaxf(y, 0.f);
    y = dw * rstd * gm.w + lb.w; res.w = xin.w + fmaxf(y, 0.f);
    *(float4*)(out + (size_t)n * HID + c) = res;
}

// ---------------- launch ----------------
extern "C" void kernel_launch(void* const* d_in, const int* in_sizes, int n_in,
                              void* d_out, int out_size)
{
    const float* edge_state = (const float*)d_in[0];
    const void*  idx        = d_in[1];
    const float* angle      = (const float*)d_in[2];
    const float* Wq = (const float*)d_in[3];
    const float* bq = (const float*)d_in[4];
    const float* Wk = (const float*)d_in[5];
    const float* bk = (const float*)d_in[6];
    const float* Wv = (const float*)d_in[7];
    const float* bv = (const float*)d_in[8];
    const float* We = (const float*)d_in[9];
    const float* Ws = (const float*)d_in[10];
    const float* bs = (const float*)d_in[11];
    const float* Wbeta = (const float*)d_in[12];
    const float* gamma = (const float*)d_in[13];
    const float* lbeta = (const float*)d_in[14];

    int N = in_sizes[0] / HID;
    int E = in_sizes[2] / HID;

    cudaFuncSetAttribute(node_hmma_kernel, cudaFuncAttributeMaxDynamicSharedMemorySize, SM_TOTAL);
    cudaFuncSetAttribute(egemm_hmma_kernel, cudaFuncAttributeMaxDynamicSharedMemorySize, SM_TOTAL);

    detect_kernel<<<1, 32>>>(idx, (long long)in_sizes[1]);
    zero_kernel<<<512, 256>>>(N);
    prep_w_kernel<<<5, 128>>>(Wq, Wk, Wv, Ws, We);

    node_hmma_kernel<<<(N + 127) / 128, 256, SM_TOTAL>>>(edge_state, bq, bk, bv, bs, N);

    egemm_hmma_kernel<<<(E + 127) / 128, 256, SM_TOTAL>>>(angle, E);

    attn_kernel<<<(E * 4 + 255) / 256, 256>>>(idx, E);

    finalize_kernel<<<(N + 7) / 8, 256>>>(edge_state, Wbeta, gamma, lbeta,
                                          (float*)d_out, N);
}

// round 7
// speedup vs baseline: 1.4190x; 1.1500x over previous
#include <cuda_runtime.h>
#include <cuda_bf16.h>
#include <cstdint>

#define HID 128
#define NHEAD 8
#define HD 16
#define MAXN 50000
#define MAXE 500000

typedef unsigned long long ull;

// ---------------- static device scratch ----------------
__device__ float g_q[MAXN * HID];
__device__ float g_k[MAXN * HID];
__device__ float g_v[MAXN * HID];
__device__ float g_xr[MAXN * HID];
__device__ float g_num[MAXN * HID];
__device__ float g_z[MAXN * NHEAD];
__device__ float g_e[(size_t)MAXE * HID];     // 256MB streaming e buffer
__device__ int   g_is64;
// CSR by destination
__device__ int g_deg[MAXN];
__device__ int g_off[MAXN + 1];
__device__ int g_pos[MAXN];
__device__ int g_elist[MAXE];
// 5 weights: 4 chunks each (hi-half0, hi-half1, lo-half0, lo-half1), 64x128 bf16 swizzled
__device__ __nv_bfloat16 g_wt[5][4][64 * 128];

// ---------------- helpers ----------------
__device__ __forceinline__ uint32_t smem_u32(const void* p) {
    uint32_t a;
    asm("{ .reg .u64 t; cvta.to.shared.u64 t, %1; cvt.u32.u64 %0, t; }" : "=r"(a) : "l"(p));
    return a;
}

// A tile [128 rows x 128 k] bf16: two 64-k blocks of 16KB, 128B rows, XOR swizzle
__device__ __forceinline__ uint32_t swzA(int row, int k) {
    uint32_t off = ((uint32_t)(k >> 6) << 14) + ((uint32_t)row << 7) + ((uint32_t)(k & 63) << 1);
    return off ^ ((off >> 3) & 0x70);
}
// B tile [64 rows x 128 k] bf16: two 64-k blocks of 8KB
__device__ __forceinline__ uint32_t swzB(int row, int k) {
    uint32_t off = ((uint32_t)(k >> 6) << 13) + ((uint32_t)row << 7) + ((uint32_t)(k & 63) << 1);
    return off ^ ((off >> 3) & 0x70);
}

__device__ __forceinline__ void ldsm4(uint32_t* r, uint32_t addr) {
    asm volatile("ldmatrix.sync.aligned.m8n8.x4.shared.b16 {%0,%1,%2,%3}, [%4];"
                 : "=r"(r[0]), "=r"(r[1]), "=r"(r[2]), "=r"(r[3]) : "r"(addr));
}

__device__ __forceinline__ void mma_bf16(float* d, const uint32_t* a, uint32_t b0, uint32_t b1) {
    asm("mma.sync.aligned.m16n8k16.row.col.f32.bf16.bf16.f32 "
        "{%0,%1,%2,%3}, {%4,%5,%6,%7}, {%8,%9}, {%0,%1,%2,%3};"
        : "+f"(d[0]), "+f"(d[1]), "+f"(d[2]), "+f"(d[3])
        : "r"(a[0]), "r"(a[1]), "r"(a[2]), "r"(a[3]), "r"(b0), "r"(b1));
}

// smem layout (GEMM kernels)
#define SM_AHI  0
#define SM_ALO  32768
#define SM_BHI  65536
#define SM_BLO  81920
#define SM_TOTAL 98304

// ---------------- small kernels ----------------
__global__ void detect_kernel(const void* idx, long long total_elems) {
    if (threadIdx.x == 0 && blockIdx.x == 0) {
        const long long* p = (const long long*)idx;
        long long n = total_elems / 2;
        if (n > 256) n = 256;
        int is64 = 1;
        for (long long i = 0; i < n; i++) {
            long long v = p[i];
            if (v < 0 || v >= (1LL << 31)) is64 = 0;
        }
        g_is64 = is64;
    }
}

__global__ void zero_deg_kernel(int N) {
    int i = blockIdx.x * blockDim.x + threadIdx.x;
    if (i < N) g_deg[i] = 0;
}

__global__ void count_kernel(const void* __restrict__ idx, int E) {
    int e = blockIdx.x * 256 + threadIdx.x;
    if (e >= E) return;
    int d;
    if (g_is64) d = (int)((const long long*)idx)[e + E];
    else        d = ((const int*)idx)[e + E];
    atomicAdd(&g_deg[d], 1);
}

// single-block exclusive scan over g_deg -> g_off, g_pos
__global__ void scan_kernel(int N, int E) {
    __shared__ int sums[1024];
    int t = threadIdx.x;
    int C = (N + 1023) / 1024;
    int b = t * C;
    int hi = b + C; if (hi > N) hi = N;
    int s = 0;
    for (int i = b; i < hi; i++) s += g_deg[i];
    sums[t] = s;
    __syncthreads();
    for (int ofs = 1; ofs < 1024; ofs <<= 1) {
        int v = (t >= ofs) ? sums[t - ofs] : 0;
        __syncthreads();
        sums[t] += v;
        __syncthreads();
    }
    int run = (t == 0) ? 0 : sums[t - 1];
    for (int i = b; i < hi; i++) {
        g_off[i] = run;
        g_pos[i] = run;
        run += g_deg[i];
    }
    if (t == 1023) g_off[N] = E;
}

__global__ void scatter_kernel(const void* __restrict__ idx, int E) {
    int e = blockIdx.x * 256 + threadIdx.x;
    if (e >= E) return;
    int d;
    if (g_is64) d = (int)((const long long*)idx)[e + E];
    else        d = ((const int*)idx)[e + E];
    int p = atomicAdd(&g_pos[d], 1);
    g_elist[p] = e;
}

// W ([in=128,out=128] row-major) -> B[n][k]=W[k][n]; hi/lo bf16; per-half swizzled chunks
__global__ void prep_w_kernel(const float* W0, const float* W1, const float* W2,
                              const float* W3, const float* W4) {
    const float* W = W0;
    if (blockIdx.x == 1) W = W1;
    else if (blockIdx.x == 2) W = W2;
    else if (blockIdx.x == 3) W = W3;
    else if (blockIdx.x == 4) W = W4;
    for (int i = threadIdx.x; i < 128 * 128; i += blockDim.x) {
        int n = i & 127, k = i >> 7;
        float x = W[k * 128 + n];               // coalesced over n
        __nv_bfloat16 hv = __float2bfloat16(x);
        __nv_bfloat16 lv = __float2bfloat16(x - __bfloat162float(hv));
        int half = n >> 6, n64 = n & 63;
        uint32_t sw = swzB(n64, k);
        *(__nv_bfloat16*)((char*)g_wt[blockIdx.x][half]     + sw) = hv;
        *(__nv_bfloat16*)((char*)g_wt[blockIdx.x][2 + half] + sw) = lv;
    }
}

// ---------------- staging ----------------
__device__ __forceinline__ void stage_A(const float* __restrict__ Asrc, int rows_valid,
                                        char* sm, int tid)
{
    char* Ahi = sm + SM_AHI;
    char* Alo = sm + SM_ALO;
    for (int i = tid; i < 4096; i += 256) {
        int r = i >> 5;
        int c4 = (i & 31) << 2;
        float4 x;
        if (r < rows_valid) x = *(const float4*)(Asrc + (size_t)r * HID + c4);
        else x = make_float4(0.f, 0.f, 0.f, 0.f);
        __nv_bfloat162 h01, h23, l01, l23;
        float hx, hy;
        h01.x = __float2bfloat16(x.x); hx = __bfloat162float(h01.x);
        h01.y = __float2bfloat16(x.y); hy = __bfloat162float(h01.y);
        l01.x = __float2bfloat16(x.x - hx);
        l01.y = __float2bfloat16(x.y - hy);
        h23.x = __float2bfloat16(x.z); hx = __bfloat162float(h23.x);
        h23.y = __float2bfloat16(x.w); hy = __bfloat162float(h23.y);
        l23.x = __float2bfloat16(x.z - hx);
        l23.y = __float2bfloat16(x.w - hy);
        uint32_t sw = swzA(r, c4);
        *(__nv_bfloat162*)(Ahi + sw)     = h01;
        *(__nv_bfloat162*)(Ahi + sw + 4) = h23;
        *(__nv_bfloat162*)(Alo + sw)     = l01;
        *(__nv_bfloat162*)(Alo + sw + 4) = l23;
    }
}

__device__ __forceinline__ void stage_B(int wi, int h, char* sm, int tid)
{
    const float4* sH = (const float4*)g_wt[wi][h];
    const float4* sL = (const float4*)g_wt[wi][2 + h];
    float4* dH = (float4*)(sm + SM_BHI);
    float4* dL = (float4*)(sm + SM_BLO);
    for (int i = tid; i < 1024; i += 256) { dH[i] = sH[i]; dL[i] = sL[i]; }
}

// ---------------- HMMA mainloop: warp tile 32x32, 3-pass bf16 hi/lo ----------------
__device__ __forceinline__ void hmma_loop(uint32_t smb, int lane, int wm, int wn,
                                          float acc[2][4][4])
{
#pragma unroll
    for (int mi = 0; mi < 2; mi++)
#pragma unroll
        for (int nj = 0; nj < 4; nj++)
#pragma unroll
            for (int t = 0; t < 4; t++) acc[mi][nj][t] = 0.f;

    int arow = wm + (lane & 15);
    int acoff = (lane >> 4) << 3;
    int brow = wn + ((lane >> 4) << 3) + (lane & 7);
    int bcoff = lane & 8;

#pragma unroll
    for (int ks = 0; ks < 8; ks++) {
        int k0 = ks * 16;
        uint32_t aoff0 = swzA(arow, k0 + acoff);
        uint32_t aoff1 = swzA(arow + 16, k0 + acoff);
        uint32_t ahi[2][4], alo[2][4];
        ldsm4(ahi[0], smb + SM_AHI + aoff0);
        ldsm4(ahi[1], smb + SM_AHI + aoff1);
        ldsm4(alo[0], smb + SM_ALO + aoff0);
        ldsm4(alo[1], smb + SM_ALO + aoff1);

        uint32_t bhi[2][4], blo[2][4];
#pragma unroll
        for (int p = 0; p < 2; p++) {
            uint32_t boff = swzB(brow + p * 16, k0 + bcoff);
            ldsm4(bhi[p], smb + SM_BHI + boff);
            ldsm4(blo[p], smb + SM_BLO + boff);
        }

#pragma unroll
        for (int mi = 0; mi < 2; mi++) {
#pragma unroll
            for (int nj = 0; nj < 4; nj++) {
                int p = nj >> 1, hh = (nj & 1) * 2;
                mma_bf16(acc[mi][nj], ahi[mi], bhi[p][hh], bhi[p][hh + 1]);
                mma_bf16(acc[mi][nj], ahi[mi], blo[p][hh], blo[p][hh + 1]);
                mma_bf16(acc[mi][nj], alo[mi], bhi[p][hh], bhi[p][hh + 1]);
            }
        }
    }
}

// ---------------- node kernel: 4 fused projections, BN=64 halves ----------------
__global__ __launch_bounds__(256, 2) void node_hmma_kernel(
    const float* __restrict__ X,
    const float* __restrict__ bq, const float* __restrict__ bk,
    const float* __restrict__ bv, const float* __restrict__ bs, int M)
{
    extern __shared__ char sm[];
    uint32_t smb = smem_u32(sm);
    int tid = threadIdx.x;
    int lane = tid & 31, w = tid >> 5;
    int wm = (w & 3) * 32, wn = (w >> 2) * 32;
    int mBase = blockIdx.x * 128;
    int rv = M - mBase; if (rv > 128) rv = 128;

    stage_A(X + (size_t)mBase * HID, rv, sm, tid);

    const float* biases[4] = {bq, bk, bv, bs};
    float* outs[4] = {g_q, g_k, g_v, g_xr};

#pragma unroll 1
    for (int wi = 0; wi < 4; wi++) {
#pragma unroll 1
        for (int h = 0; h < 2; h++) {
            __syncthreads();
            stage_B(wi, h, sm, tid);
            __syncthreads();

            float acc[2][4][4];
            hmma_loop(smb, lane, wm, wn, acc);

            const float* bias = biases[wi];
            float* out = outs[wi];
            int r0 = mBase + wm + (lane >> 2);
            int cbase = h * 64 + wn + (lane & 3) * 2;
#pragma unroll
            for (int mi = 0; mi < 2; mi++) {
#pragma unroll
                for (int nj = 0; nj < 4; nj++) {
                    int c = cbase + nj * 8;
                    float b0 = __ldg(bias + c), b1 = __ldg(bias + c + 1);
                    int r = r0 + mi * 16;
                    if (r < M)
                        *(float2*)(out + (size_t)r * HID + c) =
                            make_float2(acc[mi][nj][0] + b0, acc[mi][nj][1] + b1);
                    if (r + 8 < M)
                        *(float2*)(out + (size_t)(r + 8) * HID + c) =
                            make_float2(acc[mi][nj][2] + b0, acc[mi][nj][3] + b1);
                }
            }
        }
    }
}

// ---------------- e-GEMM kernel: e = angle @ We -> g_e (streaming stores) ----------------
__global__ __launch_bounds__(256, 2) void egemm_hmma_kernel(
    const float* __restrict__ angle, int E)
{
    extern __shared__ char sm[];
    uint32_t smb = smem_u32(sm);
    int tid = threadIdx.x;
    int lane = tid & 31, w = tid >> 5;
    int wm = (w & 3) * 32, wn = (w >> 2) * 32;
    int eBase = blockIdx.x * 128;
    int rv = E - eBase; if (rv > 128) rv = 128;

    stage_A(angle + (size_t)eBase * HID, rv, sm, tid);

#pragma unroll 1
    for (int h = 0; h < 2; h++) {
        __syncthreads();
        stage_B(4, h, sm, tid);
        __syncthreads();

        float acc[2][4][4];
        hmma_loop(smb, lane, wm, wn, acc);

        int r0 = eBase + wm + (lane >> 2);
        int cbase = h * 64 + wn + (lane & 3) * 2;
#pragma unroll
        for (int mi = 0; mi < 2; mi++) {
#pragma unroll
            for (int nj = 0; nj < 4; nj++) {
                int c = cbase + nj * 8;
                int r = r0 + mi * 16;
                if (r < E)
                    __stcs((float2*)(g_e + (size_t)r * HID + c),
                           make_float2(acc[mi][nj][0], acc[mi][nj][1]));
                if (r + 8 < E)
                    __stcs((float2*)(g_e + (size_t)(r + 8) * HID + c),
                           make_float2(acc[mi][nj][2], acc[mi][nj][3]));
            }
        }
    }
}

// ---------------- attention gather: warp per node, zero atomics ----------------
__global__ __launch_bounds__(256) void attn_gather_kernel(const void* __restrict__ idx,
                                                          int N, int E)
{
    int warp = threadIdx.x >> 5;
    int lane = threadIdx.x & 31;
    int n = blockIdx.x * 8 + warp;
    if (n >= N) return;
    int c = lane * 4;

    float4 q4 = *(const float4*)(g_q + (size_t)n * HID + c);
    float4 acc = make_float4(0.f, 0.f, 0.f, 0.f);
    float zacc = 0.f;

    int beg = g_off[n], end = g_off[n + 1];
    const long long* p64 = (const long long*)idx;
    const int* p32 = (const int*)idx;
    int is64 = g_is64;

    for (int i = beg; i < end; i++) {
        int eid = g_elist[i];
        long long s = is64 ? p64[eid] : (long long)p32[eid];
        float4 k4 = *(const float4*)(g_k + (size_t)s * HID + c);
        float4 v4 = *(const float4*)(g_v + (size_t)s * HID + c);
        float4 e4 = __ldcs((const float4*)(g_e + (size_t)eid * HID + c));

        float part = q4.x * (k4.x + e4.x) + q4.y * (k4.y + e4.y)
                   + q4.z * (k4.z + e4.z) + q4.w * (k4.w + e4.w);
        part += __shfl_xor_sync(0xffffffffu, part, 1);
        part += __shfl_xor_sync(0xffffffffu, part, 2);
        float a = __expf(part * 0.25f);   // /sqrt(16); alpha bounded, no max-shift needed
        zacc += a;
        acc.x += a * (v4.x + e4.x);
        acc.y += a * (v4.y + e4.y);
        acc.z += a * (v4.z + e4.z);
        acc.w += a * (v4.w + e4.w);
    }

    *(float4*)(g_num + (size_t)n * HID + c) = acc;
    if ((lane & 3) == 0) g_z[(size_t)n * NHEAD + (lane >> 2)] = zacc;
}

// ---------------- finalize ----------------
__global__ __launch_bounds__(256) void finalize_kernel(
    const float* __restrict__ x, const float* __restrict__ Wbeta,
    const float* __restrict__ gamma, const float* __restrict__ lbeta,
    float* __restrict__ out, int N)
{
    int warp = threadIdx.x >> 5;
    int lane = threadIdx.x & 31;
    int n = blockIdx.x * 8 + warp;
    if (n >= N) return;
    int c = lane * 4;

    float4 num = *(const float4*)(g_num + (size_t)n * HID + c);
    float z = g_z[(size_t)n * NHEAD + (lane >> 2)];
    float inv = z > 0.f ? 1.f / z : 0.f;
    float4 o = make_float4(num.x * inv, num.y * inv, num.z * inv, num.w * inv);
    float4 xr = *(const float4*)(g_xr + (size_t)n * HID + c);

    float4 wb0 = *(const float4*)(Wbeta + c);
    float4 wb1 = *(const float4*)(Wbeta + 128 + c);
    float4 wb2 = *(const float4*)(Wbeta + 256 + c);
    float dot = o.x * wb0.x + o.y * wb0.y + o.z * wb0.z + o.w * wb0.w
              + xr.x * wb1.x + xr.y * wb1.y + xr.z * wb1.z + xr.w * wb1.w
              + (o.x - xr.x) * wb2.x + (o.y - xr.y) * wb2.y
              + (o.z - xr.z) * wb2.z + (o.w - xr.w) * wb2.w;
#pragma unroll
    for (int m = 16; m; m >>= 1) dot += __shfl_xor_sync(0xffffffffu, dot, m);
    float beta = 1.f / (1.f + __expf(-dot));

    float4 g;
    g.x = beta * xr.x + (1.f - beta) * o.x;
    g.y = beta * xr.y + (1.f - beta) * o.y;
    g.z = beta * xr.z + (1.f - beta) * o.z;
    g.w = beta * xr.w + (1.f - beta) * o.w;

    float sgm = g.x + g.y + g.z + g.w;
#pragma unroll
    for (int m = 16; m; m >>= 1) sgm += __shfl_xor_sync(0xffffffffu, sgm, m);
    float mu = sgm * (1.f / 128.f);

    float dx = g.x - mu, dy = g.y - mu, dz = g.z - mu, dw = g.w - mu;
    float vs = dx * dx + dy * dy + dz * dz + dw * dw;
#pragma unroll
    for (int m = 16; m; m >>= 1) vs += __shfl_xor_sync(0xffffffffu, vs, m);
    float rstd = rsqrtf(vs * (1.f / 128.f) + 1e-5f);

    float4 gm = *(const float4*)(gamma + c);
    float4 lb = *(const float4*)(lbeta + c);
    float4 xin = *(const float4*)(x + (size_t)n * HID + c);

    float4 res;
    float y;
    y = dx * rstd * gm.x + lb.x; res.x = xin.x + fmaxf(y, 0.f);
    y = dy * rstd * gm.y + lb.y; res.y = xin.y + fmaxf(y, 0.f);
    y = dz * rstd * gm.z + lb.z; res.z = xin.z + fmaxf(y, 0.f);
    y = dw * rstd * gm.w + lb.w; res.w = xin.w + fmaxf(y, 0.f);
    *(float4*)(out + (size_t)n * HID + c) = res;
}

// ---------------- launch ----------------
extern "C" void kernel_launch(void* const* d_in, const int* in_sizes, int n_in,
                              void* d_out, int out_size)
{
    const float* edge_state = (const float*)d_in[0];
    const void*  idx        = d_in[1];
    const float* angle      = (const float*)d_in[2];
    const float* Wq = (const float*)d_in[3];
    const float* bq = (const float*)d_in[4];
    const float* Wk = (const float*)d_in[5];
    const float* bk = (const float*)d_in[6];
    const float* Wv = (const float*)d_in[7];
    const float* bv = (const float*)d_in[8];
    const float* We = (const float*)d_in[9];
    const float* Ws = (const float*)d_in[10];
    const float* bs = (const float*)d_in[11];
    const float* Wbeta = (const float*)d_in[12];
    const float* gamma = (const float*)d_in[13];
    const float* lbeta = (const float*)d_in[14];

    int N = in_sizes[0] / HID;
    int E = in_sizes[2] / HID;

    cudaFuncSetAttribute(node_hmma_kernel, cudaFuncAttributeMaxDynamicSharedMemorySize, SM_TOTAL);
    cudaFuncSetAttribute(egemm_hmma_kernel, cudaFuncAttributeMaxDynamicSharedMemorySize, SM_TOTAL);

    detect_kernel<<<1, 32>>>(idx, (long long)in_sizes[1]);
    prep_w_kernel<<<5, 128>>>(Wq, Wk, Wv, Ws, We);

    // CSR build (by destination)
    zero_deg_kernel<<<(N + 255) / 256, 256>>>(N);
    count_kernel<<<(E + 255) / 256, 256>>>(idx, E);
    scan_kernel<<<1, 1024>>>(N, E);
    scatter_kernel<<<(E + 255) / 256, 256>>>(idx, E);

    node_hmma_kernel<<<(N + 127) / 128, 256, SM_TOTAL>>>(edge_state, bq, bk, bv, bs, N);

    egemm_hmma_kernel<<<(E + 127) / 128, 256, SM_TOTAL>>>(angle, E);

    attn_gather_kernel<<<(N + 7) / 8, 256>>>(idx, N, E);

    finalize_kernel<<<(N + 7) / 8, 256>>>(edge_state, Wbeta, gamma, lbeta,
                                          (float*)d_out, N);
}